// round 11
// baseline (speedup 1.0000x reference)
#include <cuda_runtime.h>
#include <math.h>
#include <stdint.h>

#define TT 512
#define NN 256
#define CC 256
#define SS 48
#define LL 97
#define LOG2E 1.4426950408889634f
#define LN2   0.6931471805599453f

#define CHUNK 16                    // timesteps per ring buffer
#define NBUF 4
#define NCHUNK (TT / CHUNK)         // 32
#define GRID NN                     // one batch row per CTA
#define SLOTS 64                    // floats per timestep tile
#define GW 8                        // gather warps (wid 0..7), each 2 timesteps/chunk
#define CW 1                        // compute warp (wid 8) - hi-wid = arbiter priority
#define NWARPS (GW + CW)
#define NTHREADS (NWARPS * 32)      // 288
#define BUF_F (CHUNK * SLOTS)       // 1024 floats per buffer
#define RING_F (NBUF * BUF_F)       // 4096 floats = 16 KB
#define SCRATCH_F (GW * 512)        // 8 warps x 2 t x 256 floats = 16 KB
#define SMEM_BYTES ((RING_F + SCRATCH_F) * 4)   // 32768

__device__ float g_loss_n[NN];
__device__ int   g_count;           // zero-init; self-resetting per launch

__device__ __forceinline__ uint32_t s2u(const void* p) {
    return (uint32_t)__cvta_generic_to_shared(p);
}
__device__ __forceinline__ float ex2f(float x) {
    float y; asm("ex2.approx.ftz.f32 %0, %1;" : "=f"(y) : "f"(x)); return y;
}
__device__ __forceinline__ float lg2f(float x) {
    float y; asm("lg2.approx.ftz.f32 %0, %1;" : "=f"(y) : "f"(x)); return y;
}
__device__ __forceinline__ void mbar_wait(uint32_t addr, uint32_t parity) {
    asm volatile(
        "{\n"
        ".reg .pred P;\n"
        "WL%=:\n"
        "mbarrier.try_wait.parity.acquire.cta.shared::cta.b64 P, [%0], %1, 0x989680;\n"
        "@P bra WD%=;\n"
        "bra WL%=;\n"
        "WD%=:\n"
        "}\n" :: "r"(addr), "r"(parity) : "memory");
}

struct AState { float a0, a1, a2, a3, xs; int X; };

__device__ __forceinline__ void alpha_step(AState& s, float pb, float pa, float pc,
                                           float sk1f, float sk3f)
{
    float p3 = __shfl_up_sync(0xffffffffu, s.a3, 1);
    float q3 = p3 * s.xs;                  // neighbor a3 rescaled (0 on lane 0)
    float t01 = s.a0 + s.a1;
    float t23 = s.a2 + s.a3;
    float n0v = (s.a0 + q3) * pb;
    float n1v = fmaf(sk1f, q3, t01) * pa;
    float n2v = (s.a1 + s.a2) * pb;
    float n3v = fmaf(sk3f, s.a1, t23) * pc;
    s.a0 = n0v; s.a1 = n1v; s.a2 = n2v; s.a3 = n3v;
}

// PROVEN two-shfl renorm: second shfl broadcasts FINAL post-adoption X.
__device__ __forceinline__ void renorm(AState& s, int lane)
{
    float mx = fmaxf(fmaxf(s.a0, s.a1), fmaxf(s.a2, s.a3));
    int Xp = __shfl_up_sync(0xffffffffu, s.X, 1);      // neighbor X (pre-update)
    int e  = (int)(__float_as_uint(mx) >> 23);
    int eu = (e > 0) ? e : 127;
    int Xn = s.X + (eu - 127);
    Xn = (mx == 0.0f && lane > 0) ? Xp : Xn;           // empty lanes adopt neighbor frame
    float scale = __uint_as_float((unsigned)(254 - eu) << 23);
    s.a0 *= scale; s.a1 *= scale; s.a2 *= scale; s.a3 *= scale;
    s.X = Xn;
    int Xp2 = __shfl_up_sync(0xffffffffu, s.X, 1);     // neighbor FINAL X
    int d = min(126, max(-126, Xp2 - s.X));
    float x = __uint_as_float((unsigned)(d + 127) << 23);
    s.xs = (lane == 0) ? 0.0f : x;
}

__global__ __launch_bounds__(NTHREADS, 2)
void ctc_fused(const float* __restrict__ logits,
               const int*   __restrict__ labels,
               const int*   __restrict__ pred_sizes,
               const int*   __restrict__ tgt_sizes,
               float*       __restrict__ out)
{
    extern __shared__ __align__(128) float smem[];
    float* ring    = smem;                 // RING_F floats
    float* scratch = smem + RING_F;        // SCRATCH_F floats
    __shared__ __align__(8) unsigned long long mb_full[NBUF];
    __shared__ __align__(8) unsigned long long mb_empty[NBUF];
    __shared__ float red[NWARPS];
    __shared__ int s_last;

    const int tid  = threadIdx.x;
    const int wid  = tid >> 5;
    const int lane = tid & 31;
    const int n    = blockIdx.x;           // one batch row per CTA

    if (tid == 0) {
        #pragma unroll
        for (int b = 0; b < NBUF; b++) {
            asm volatile("mbarrier.init.shared.b64 [%0], %1;" :: "r"(s2u(&mb_full[b])),  "r"(GW));
            asm volatile("mbarrier.init.shared.b64 [%0], %1;" :: "r"(s2u(&mb_empty[b])), "r"(CW));
        }
    }
    __syncthreads();

    if (wid < GW) {
        // ================= gather warps (2 timesteps per chunk each) =================
        float* myscr = scratch + wid * 512;           // 2 t-slots x 256 floats
        int ch0 = 0, ch1 = 0;
        if (lane < 24) {
            int2 l0 = *(const int2*)(labels + n * SS + 2 * lane);
            ch0 = l0.x; ch1 = l0.y;
        }
        // prologue: load chunk 0 rows into registers
        float4 ra0, ra1, rb0, rb1;
        {
            const float4* sa = (const float4*)(logits + ((size_t)wid       * NN + n) * CC);
            const float4* sb = (const float4*)(logits + ((size_t)(wid + 8) * NN + n) * CC);
            ra0 = sa[lane]; ra1 = sa[lane + 32];
            rb0 = sb[lane]; rb1 = sb[lane + 32];
        }
        #pragma unroll 1
        for (int c = 0; c < NCHUNK; c++) {
            const int b = c % NBUF;
            if (c >= NBUF) mbar_wait(s2u(&mb_empty[b]), ((c / NBUF) - 1) & 1);
            // park current chunk's rows in scratch
            float4* d0 = (float4*)myscr;
            d0[lane] = ra0; d0[lane + 32] = ra1;
            float4* d1 = (float4*)(myscr + 256);
            d1[lane] = rb0; d1[lane + 32] = rb1;
            __syncwarp();
            // issue NEXT chunk's loads immediately (hide DRAM latency behind scatter)
            if (c + 1 < NCHUNK) {
                const int ta = (c + 1) * CHUNK + wid;
                const float4* sa = (const float4*)(logits + ((size_t)ta       * NN + n) * CC);
                const float4* sb = (const float4*)(logits + ((size_t)(ta + 8) * NN + n) * CC);
                ra0 = sa[lane]; ra1 = sa[lane + 32];
                rb0 = sb[lane]; rb1 = sb[lane + 32];
            }
            // gather 49 channels -> linear probs -> ring
            if (lane <= 24) {
                #pragma unroll
                for (int s = 0; s < 2; s++) {
                    const float* base = myscr + s * 256;
                    const int j = wid + s * 8;
                    float p0 = ex2f(base[ch0] * LOG2E);
                    float p1 = ex2f(base[ch1] * LOG2E);
                    float* tp = ring + (size_t)(b * CHUNK + j) * SLOTS;
                    *(float2*)(tp + 2 * lane) = make_float2(p0, p1);
                }
            }
            __syncwarp();
            if (lane == 0)
                asm volatile("mbarrier.arrive.shared.b64 _, [%0];" :: "r"(s2u(&mb_full[b])) : "memory");
        }
    } else {
        // ================= compute warp =================
        int lab_a = (2 * lane     < SS) ? labels[n * SS + 2 * lane]     : 0;
        int lab_b = (2 * lane + 1 < SS) ? labels[n * SS + 2 * lane + 1] : 0;
        int lab_p = (2 * lane - 1 >= 0) ? labels[n * SS + 2 * lane - 1] : 0;
        const float sk1f = ((lab_a != 0) && (lab_a != lab_p)) ? 1.0f : 0.0f;
        const float sk3f = ((lab_b != 0) && (lab_b != lab_a)) ? 1.0f : 0.0f;
        const int in_len = pred_sizes[n];
        const int pair_off = (lane < 24) ? 2 * lane : 48;

        AState s;
        s.a0 = 0.0f; s.a1 = 0.0f; s.a2 = 0.0f; s.a3 = 0.0f;
        s.X = 0;
        s.xs = (lane == 0) ? 0.0f : 1.0f;

        #pragma unroll 1
        for (int c = 0; c < NCHUNK; c++) {
            const int b = c % NBUF;
            mbar_wait(s2u(&mb_full[b]), (c / NBUF) & 1);
            const float* base = ring + (size_t)(b * CHUNK) * SLOTS;
            const bool fast = (c > 0) && ((c + 1) * CHUNK <= in_len);

            if (fast) {
                #pragma unroll
                for (int h = 0; h < 2; h++) {
                    float pa[8], pc[8], pb[8];
                    #pragma unroll
                    for (int j = 0; j < 8; j++) {
                        const float* rp = base + (h * 8 + j) * SLOTS;
                        float2 f2 = *(const float2*)(rp + pair_off);
                        pa[j] = f2.x; pc[j] = f2.y;
                        pb[j] = rp[48];
                    }
                    #pragma unroll
                    for (int j = 0; j < 8; j++) {
                        alpha_step(s, pb[j], pa[j], pc[j], sk1f, sk3f);
                        if ((j & 3) == 3) renorm(s, lane);
                    }
                }
            } else {
                #pragma unroll 1
                for (int j = 0; j < CHUNK; j++) {
                    const int t = c * CHUNK + j;
                    const float* rp = base + j * SLOTS;
                    if (t < in_len) {
                        float2 f2 = *(const float2*)(rp + pair_off);
                        float pbv = rp[48];
                        if (t == 0) {
                            if (lane == 0) { s.a0 = pbv; s.a1 = f2.x; }
                        } else {
                            alpha_step(s, pbv, f2.x, f2.y, sk1f, sk3f);
                        }
                        if ((t & 3) == 3) renorm(s, lane);
                    }
                }
            }

            if (lane == 0)
                asm volatile("mbarrier.arrive.shared.b64 _, [%0];" :: "r"(s2u(&mb_empty[b])) : "memory");
        }

        // per-row loss: true log2(alpha_l) = lg2(stored) + X_lane
        {
            int tl = tgt_sizes[n];
            int i1 = 2 * tl - 1, i2 = 2 * tl;
            int sel1 = i1 & 3, sl1 = i1 >> 2;
            float x1 = (sel1 == 0) ? s.a0 : (sel1 == 1) ? s.a1 : (sel1 == 2) ? s.a2 : s.a3;
            x1 = __shfl_sync(0xffffffffu, x1, sl1);
            float X1 = (float)__shfl_sync(0xffffffffu, s.X, sl1);
            int sel2 = i2 & 3, sl2 = i2 >> 2;
            float x2 = (sel2 == 0) ? s.a0 : (sel2 == 1) ? s.a1 : (sel2 == 2) ? s.a2 : s.a3;
            x2 = __shfl_sync(0xffffffffu, x2, sl2);
            float X2 = (float)__shfl_sync(0xffffffffu, s.X, sl2);
            float l1 = lg2f(x1) + X1;
            float l2 = lg2f(x2) + X2;
            float m  = fmaxf(l1, l2);
            float dd = fminf(l1, l2) - m;
            float lt = m + lg2f(1.0f + ex2f(dd));
            float loss = -LN2 * lt;
            if (!(loss <= 1e29f)) loss = 0.0f;      // inf/NaN -> 0 (zero_infinity)
            if (lane == 0) g_loss_n[n] = loss / (float)tl;
        }
    }

    // fused mean-reduction: last CTA to finish does it
    __syncthreads();
    if (tid == 0) {
        __threadfence();
        int old = atomicAdd(&g_count, 1);
        s_last = (old == (int)gridDim.x - 1) ? 1 : 0;
    }
    __syncthreads();
    if (s_last) {
        __threadfence();
        float v = 0.0f;
        for (int i = tid; i < NN; i += NTHREADS) v += __ldcg(&g_loss_n[i]);
        #pragma unroll
        for (int o = 16; o; o >>= 1) v += __shfl_down_sync(0xffffffffu, v, o);
        if (lane == 0) red[wid] = v;
        __syncthreads();
        if (tid == 0) {
            float m = 0.0f;
            #pragma unroll
            for (int w = 0; w < NWARPS; w++) m += red[w];
            m /= (float)NN;
            if (isnan(m) || isinf(m)) m = 0.0f;
            out[0] = m;
            g_count = 0;   // reset for next graph replay
        }
    }
}

extern "C" void kernel_launch(void* const* d_in, const int* in_sizes, int n_in,
                              void* d_out, int out_size)
{
    const float* logits     = (const float*)d_in[0];
    const int*   labels     = (const int*)  d_in[1];
    const int*   pred_sizes = (const int*)  d_in[2];
    const int*   tgt_sizes  = (const int*)  d_in[3];
    float*       out        = (float*)d_out;

    cudaFuncSetAttribute(ctc_fused, cudaFuncAttributeMaxDynamicSharedMemorySize, SMEM_BYTES);
    ctc_fused<<<GRID, NTHREADS, SMEM_BYTES>>>(logits, labels, pred_sizes, tgt_sizes, out);
}

// round 12
// speedup vs baseline: 1.6245x; 1.6245x over previous
#include <cuda_runtime.h>
#include <math.h>
#include <stdint.h>

#define TT 512
#define NN 256
#define CC 256
#define SS 48
#define LL 97
#define LOG2E 1.4426950408889634f
#define LN2   0.6931471805599453f

#define ROWS 2                      // batch rows per CTA
#define CHUNK 16                    // timesteps per ring buffer
#define NBUF 4
#define NCHUNK (TT / CHUNK)         // 32
#define GRID (NN / ROWS)            // 128
#define SLOTS 64                    // floats per (t,row) tile
#define GW 8                        // gather warps (wid 0..7)
#define CW 2                        // compute warps (wid 8..9) - hi-wid priority
#define NWARPS (GW + CW)
#define NTHREADS (NWARPS * 32)      // 320
#define TILE_F (ROWS * SLOTS)       // 128 floats per timestep
#define BUF_F (CHUNK * TILE_F)      // 2048 floats per buffer
#define RING_F (NBUF * BUF_F)       // 8192 floats = 32 KB
#define SCRATCH_F (2 * GW * 1024)   // parity-double-buffered: 2 x 8 warps x 1024 floats = 64 KB
#define SMEM_BYTES ((RING_F + SCRATCH_F) * 4)   // 98304

__device__ float g_loss_n[NN];
__device__ int   g_count;           // zero-init; self-resetting per launch

__device__ __forceinline__ uint32_t s2u(const void* p) {
    return (uint32_t)__cvta_generic_to_shared(p);
}
__device__ __forceinline__ float ex2f(float x) {
    float y; asm("ex2.approx.ftz.f32 %0, %1;" : "=f"(y) : "f"(x)); return y;
}
__device__ __forceinline__ float lg2f(float x) {
    float y; asm("lg2.approx.ftz.f32 %0, %1;" : "=f"(y) : "f"(x)); return y;
}
__device__ __forceinline__ void mbar_wait(uint32_t addr, uint32_t parity) {
    asm volatile(
        "{\n"
        ".reg .pred P;\n"
        "WL%=:\n"
        "mbarrier.try_wait.parity.acquire.cta.shared::cta.b64 P, [%0], %1, 0x989680;\n"
        "@P bra WD%=;\n"
        "bra WL%=;\n"
        "WD%=:\n"
        "}\n" :: "r"(addr), "r"(parity) : "memory");
}

#define CP16(dst_u32, src_ptr) \
    asm volatile("cp.async.cg.shared.global [%0], [%1], 16;" :: "r"(dst_u32), "l"(src_ptr) : "memory")
#define CP_COMMIT() asm volatile("cp.async.commit_group;" ::: "memory")
#define CP_WAIT1()  asm volatile("cp.async.wait_group 1;" ::: "memory")
#define CP_WAIT0()  asm volatile("cp.async.wait_group 0;" ::: "memory")

struct AState { float a0, a1, a2, a3, xs; int X; };

__device__ __forceinline__ void alpha_step(AState& s, float pb, float pa, float pc,
                                           float sk1f, float sk3f)
{
    float p3 = __shfl_up_sync(0xffffffffu, s.a3, 1);
    float q3 = p3 * s.xs;                  // neighbor a3 rescaled (0 on lane 0)
    float t01 = s.a0 + s.a1;
    float t23 = s.a2 + s.a3;
    float n0v = (s.a0 + q3) * pb;
    float n1v = fmaf(sk1f, q3, t01) * pa;
    float n2v = (s.a1 + s.a2) * pb;
    float n3v = fmaf(sk3f, s.a1, t23) * pc;
    s.a0 = n0v; s.a1 = n1v; s.a2 = n2v; s.a3 = n3v;
}

// PROVEN two-shfl renorm: second shfl broadcasts FINAL post-adoption X.
__device__ __forceinline__ void renorm(AState& s, int lane)
{
    float mx = fmaxf(fmaxf(s.a0, s.a1), fmaxf(s.a2, s.a3));
    int Xp = __shfl_up_sync(0xffffffffu, s.X, 1);      // neighbor X (pre-update)
    int e  = (int)(__float_as_uint(mx) >> 23);
    int eu = (e > 0) ? e : 127;
    int Xn = s.X + (eu - 127);
    Xn = (mx == 0.0f && lane > 0) ? Xp : Xn;           // empty lanes adopt neighbor frame
    float scale = __uint_as_float((unsigned)(254 - eu) << 23);
    s.a0 *= scale; s.a1 *= scale; s.a2 *= scale; s.a3 *= scale;
    s.X = Xn;
    int Xp2 = __shfl_up_sync(0xffffffffu, s.X, 1);     // neighbor FINAL X
    int d = min(126, max(-126, Xp2 - s.X));
    float x = __uint_as_float((unsigned)(d + 127) << 23);
    s.xs = (lane == 0) ? 0.0f : x;
}

__global__ __launch_bounds__(NTHREADS, 1)
void ctc_fused(const float* __restrict__ logits,
               const int*   __restrict__ labels,
               const int*   __restrict__ pred_sizes,
               const int*   __restrict__ tgt_sizes,
               float*       __restrict__ out)
{
    extern __shared__ __align__(128) float smem[];
    float* ring    = smem;                 // RING_F floats
    float* scratch = smem + RING_F;        // SCRATCH_F floats (2 parities x GW x 1024)
    __shared__ __align__(8) unsigned long long mb_full[NBUF];
    __shared__ __align__(8) unsigned long long mb_empty[NBUF];
    __shared__ float red[NWARPS];
    __shared__ int s_last;

    const int tid  = threadIdx.x;
    const int wid  = tid >> 5;
    const int lane = tid & 31;
    const int n0   = blockIdx.x * ROWS;

    if (tid == 0) {
        #pragma unroll
        for (int b = 0; b < NBUF; b++) {
            asm volatile("mbarrier.init.shared.b64 [%0], %1;" :: "r"(s2u(&mb_full[b])),  "r"(GW));
            asm volatile("mbarrier.init.shared.b64 [%0], %1;" :: "r"(s2u(&mb_empty[b])), "r"(CW));
        }
    }
    __syncthreads();

    if (wid < GW) {
        // ================= gather warps: cp.async double-buffered pipeline =================
        // Each warp owns 2 timesteps per chunk (ta = c*CHUNK+wid, tb = ta+8); each timestep
        // is a 2 KB row-pair (rows n0, n0+1 contiguous).
        const uint32_t scr_u32 = s2u(scratch) + (uint32_t)wid * 4096u;   // + parity*32768
        float* scr_gen = scratch + wid * 1024;                           // + parity*8192

        int ch00 = 0, ch01 = 0, ch10 = 0, ch11 = 0;
        if (lane < 24) {
            int2 l0 = *(const int2*)(labels + n0 * SS + 2 * lane);
            int2 l1 = *(const int2*)(labels + (n0 + 1) * SS + 2 * lane);
            ch00 = l0.x; ch01 = l0.y; ch10 = l1.x; ch11 = l1.y;
        }

        // prologue: issue chunk 0 into parity-0 buffer
        {
            const float* sa = logits + ((size_t)(0 * CHUNK + wid) * NN + n0) * CC;
            const float* sb = logits + ((size_t)(0 * CHUNK + wid + 8) * NN + n0) * CC;
            #pragma unroll
            for (int i = 0; i < 4; i++) {
                CP16(scr_u32 + (lane + 32 * i) * 16u, sa + (lane + 32 * i) * 4);
                CP16(scr_u32 + 2048u + (lane + 32 * i) * 16u, sb + (lane + 32 * i) * 4);
            }
            CP_COMMIT();
        }

        #pragma unroll 1
        for (int c = 0; c < NCHUNK; c++) {
            const int b = c % NBUF;
            // issue NEXT chunk's copies first (stay in flight through this chunk's work)
            if (c + 1 < NCHUNK) {
                const uint32_t dst = scr_u32 + (uint32_t)(((c + 1) & 1) * 32768);
                const float* sa = logits + ((size_t)((c + 1) * CHUNK + wid) * NN + n0) * CC;
                const float* sb = logits + ((size_t)((c + 1) * CHUNK + wid + 8) * NN + n0) * CC;
                #pragma unroll
                for (int i = 0; i < 4; i++) {
                    CP16(dst + (lane + 32 * i) * 16u, sa + (lane + 32 * i) * 4);
                    CP16(dst + 2048u + (lane + 32 * i) * 16u, sb + (lane + 32 * i) * 4);
                }
                CP_COMMIT();
                CP_WAIT1();      // chunk c's group complete; c+1 still in flight
            } else {
                CP_WAIT0();
            }
            __syncwarp();

            if (c >= NBUF) mbar_wait(s2u(&mb_empty[b]), ((c / NBUF) - 1) & 1);

            // gather 49 channels per row -> linear probs -> ring
            const float* buf = scr_gen + (c & 1) * 8192;
            if (lane <= 24) {
                #pragma unroll
                for (int s = 0; s < 2; s++) {
                    const float* base = buf + s * 512;
                    const int j = wid + s * 8;
                    float p00 = ex2f(base[ch00]       * LOG2E);
                    float p01 = ex2f(base[ch01]       * LOG2E);
                    float p10 = ex2f(base[256 + ch10] * LOG2E);
                    float p11 = ex2f(base[256 + ch11] * LOG2E);
                    float* tp = ring + (size_t)(b * CHUNK + j) * TILE_F;
                    *(float2*)(tp + 2 * lane)         = make_float2(p00, p01);
                    *(float2*)(tp + SLOTS + 2 * lane) = make_float2(p10, p11);
                }
            }
            __syncwarp();
            if (lane == 0)
                asm volatile("mbarrier.arrive.shared.b64 _, [%0];" :: "r"(s2u(&mb_full[b])) : "memory");
        }
    } else {
        // ================= compute warps (one batch row each) =================
        const int row = wid - GW;
        const int n = n0 + row;
        int lab_a = (2 * lane     < SS) ? labels[n * SS + 2 * lane]     : 0;
        int lab_b = (2 * lane + 1 < SS) ? labels[n * SS + 2 * lane + 1] : 0;
        int lab_p = (2 * lane - 1 >= 0) ? labels[n * SS + 2 * lane - 1] : 0;
        const float sk1f = ((lab_a != 0) && (lab_a != lab_p)) ? 1.0f : 0.0f;
        const float sk3f = ((lab_b != 0) && (lab_b != lab_a)) ? 1.0f : 0.0f;
        const int in_len = pred_sizes[n];
        const int pair_off = (lane < 24) ? 2 * lane : 48;

        AState s;
        s.a0 = 0.0f; s.a1 = 0.0f; s.a2 = 0.0f; s.a3 = 0.0f;
        s.X = 0;
        s.xs = (lane == 0) ? 0.0f : 1.0f;

        #pragma unroll 1
        for (int c = 0; c < NCHUNK; c++) {
            const int b = c % NBUF;
            mbar_wait(s2u(&mb_full[b]), (c / NBUF) & 1);
            const float* base = ring + (size_t)(b * CHUNK) * TILE_F + row * SLOTS;
            const bool fast = (c > 0) && ((c + 1) * CHUNK <= in_len);

            if (fast) {
                #pragma unroll
                for (int h = 0; h < 2; h++) {
                    float pa[8], pc[8], pb[8];
                    #pragma unroll
                    for (int j = 0; j < 8; j++) {
                        const float* rp = base + (h * 8 + j) * TILE_F;
                        float2 f2 = *(const float2*)(rp + pair_off);
                        pa[j] = f2.x; pc[j] = f2.y;
                        pb[j] = rp[48];
                    }
                    #pragma unroll
                    for (int j = 0; j < 8; j++) {
                        alpha_step(s, pb[j], pa[j], pc[j], sk1f, sk3f);
                        if ((j & 3) == 3) renorm(s, lane);
                    }
                }
            } else {
                #pragma unroll 1
                for (int j = 0; j < CHUNK; j++) {
                    const int t = c * CHUNK + j;
                    const float* rp = base + j * TILE_F;
                    if (t < in_len) {
                        float2 f2 = *(const float2*)(rp + pair_off);
                        float pbv = rp[48];
                        if (t == 0) {
                            if (lane == 0) { s.a0 = pbv; s.a1 = f2.x; }
                        } else {
                            alpha_step(s, pbv, f2.x, f2.y, sk1f, sk3f);
                        }
                        if ((t & 3) == 3) renorm(s, lane);
                    }
                }
            }

            if (lane == 0)
                asm volatile("mbarrier.arrive.shared.b64 _, [%0];" :: "r"(s2u(&mb_empty[b])) : "memory");
        }

        // per-row loss: true log2(alpha_l) = lg2(stored) + X_lane
        {
            int tl = tgt_sizes[n];
            int i1 = 2 * tl - 1, i2 = 2 * tl;
            int sel1 = i1 & 3, sl1 = i1 >> 2;
            float x1 = (sel1 == 0) ? s.a0 : (sel1 == 1) ? s.a1 : (sel1 == 2) ? s.a2 : s.a3;
            x1 = __shfl_sync(0xffffffffu, x1, sl1);
            float X1 = (float)__shfl_sync(0xffffffffu, s.X, sl1);
            int sel2 = i2 & 3, sl2 = i2 >> 2;
            float x2 = (sel2 == 0) ? s.a0 : (sel2 == 1) ? s.a1 : (sel2 == 2) ? s.a2 : s.a3;
            x2 = __shfl_sync(0xffffffffu, x2, sl2);
            float X2 = (float)__shfl_sync(0xffffffffu, s.X, sl2);
            float l1 = lg2f(x1) + X1;
            float l2 = lg2f(x2) + X2;
            float m  = fmaxf(l1, l2);
            float dd = fminf(l1, l2) - m;
            float lt = m + lg2f(1.0f + ex2f(dd));
            float loss = -LN2 * lt;
            if (!(loss <= 1e29f)) loss = 0.0f;      // inf/NaN -> 0 (zero_infinity)
            if (lane == 0) g_loss_n[n] = loss / (float)tl;
        }
    }

    // fused mean-reduction: last CTA to finish does it
    __syncthreads();
    if (tid == 0) {
        __threadfence();
        int old = atomicAdd(&g_count, 1);
        s_last = (old == (int)gridDim.x - 1) ? 1 : 0;
    }
    __syncthreads();
    if (s_last) {
        __threadfence();
        float v = 0.0f;
        for (int i = tid; i < NN; i += NTHREADS) v += __ldcg(&g_loss_n[i]);
        #pragma unroll
        for (int o = 16; o; o >>= 1) v += __shfl_down_sync(0xffffffffu, v, o);
        if (lane == 0) red[wid] = v;
        __syncthreads();
        if (tid == 0) {
            float m = 0.0f;
            #pragma unroll
            for (int w = 0; w < NWARPS; w++) m += red[w];
            m /= (float)NN;
            if (isnan(m) || isinf(m)) m = 0.0f;
            out[0] = m;
            g_count = 0;   // reset for next graph replay
        }
    }
}

extern "C" void kernel_launch(void* const* d_in, const int* in_sizes, int n_in,
                              void* d_out, int out_size)
{
    const float* logits     = (const float*)d_in[0];
    const int*   labels     = (const int*)  d_in[1];
    const int*   pred_sizes = (const int*)  d_in[2];
    const int*   tgt_sizes  = (const int*)  d_in[3];
    float*       out        = (float*)d_out;

    cudaFuncSetAttribute(ctc_fused, cudaFuncAttributeMaxDynamicSharedMemorySize, SMEM_BYTES);
    ctc_fused<<<GRID, NTHREADS, SMEM_BYTES>>>(logits, labels, pred_sizes, tgt_sizes, out);
}